// round 3
// baseline (speedup 1.0000x reference)
#include <cuda_runtime.h>

#define B_  4
#define T_  2048
#define C_  1024
#define NH_ 16
#define D_  64
#define BT_ (B_ * T_)      // 8192
#define C3_ (3 * C_)       // 3072

// Scratch buffers (no allocation allowed) — device globals.
__device__ float g_qkv[BT_ * C3_];   // [8192, 3072]  q|k|v, biases folded, q pre-scaled by 1/sqrt(D)
__device__ float g_y[BT_ * C_];      // [8192, 1024]  attention output, head-major columns

// ---------------- packed f32x2 helpers (sm_103a FFMA2 path) ----------------
typedef unsigned long long u64;

__device__ __forceinline__ u64 pk2(float lo, float hi) {
    u64 r; asm("mov.b64 %0, {%1,%2};" : "=l"(r) : "f"(lo), "f"(hi)); return r;
}
__device__ __forceinline__ void fma2(u64 &c, u64 a, u64 b) {
    asm("fma.rn.f32x2 %0, %1, %2, %0;" : "+l"(c) : "l"(a), "l"(b));
}
__device__ __forceinline__ void mul2(u64 &c, u64 a) {
    asm("mul.rn.f32x2 %0, %0, %1;" : "+l"(c) : "l"(a));
}
__device__ __forceinline__ float2 upk(u64 v) {
    float2 f; asm("mov.b64 {%0,%1}, %2;" : "=f"(f.x), "=f"(f.y) : "l"(v)); return f;
}

// ---------------------------------------------------------------------------
// SGEMM: C[M,N] = A[M,K] @ W[K,N] + epilogue.  BM=BN=128, BK=8, 256 threads,
// 8x8 microtile (2x2 blocks of 4x4), inner product via packed f32x2 FMA.
// MODE 0: qkv epilogue (b_attn; +bQ & *0.125 for q cols; +bK for k cols)
// MODE 1: proj epilogue (b_proj)
// ---------------------------------------------------------------------------
template<int MODE>
__global__ __launch_bounds__(256) void sgemm_kernel(
    const float* __restrict__ A, const float* __restrict__ W,
    const float* __restrict__ bias,
    const float* __restrict__ bQ, const float* __restrict__ bK,
    float* __restrict__ Cout, int M, int N, int K)
{
    __shared__ float As[8][128];   // A tile transposed: As[k][m]
    __shared__ float Bs[8][128];   // B tile natural:    Bs[k][n]

    const int tid = threadIdx.x;
    const int tx = tid & 15, ty = tid >> 4;
    const int crow = blockIdx.y * 128, ccol = blockIdx.x * 128;

    const int arow = tid >> 1, acol = (tid & 1) * 4;   // 128 rows x 8 cols
    const int brow = tid >> 5, bcol = (tid & 31) * 4;  // 8 rows x 128 cols
    const float* Ag = A + (size_t)(crow + arow) * K + acol;
    const float* Wg = W + (size_t)brow * N + (ccol + bcol);

    // accumulators: 8 rows x 4 column-pairs (packed f32x2)
    u64 c2[8][4];
    #pragma unroll
    for (int i = 0; i < 8; i++)
        #pragma unroll
        for (int jp = 0; jp < 4; jp++) c2[i][jp] = 0ull;

    float4 pa = *(const float4*)Ag;
    float4 pb = *(const float4*)Wg;
    const int nk = K >> 3;

    for (int kt = 0; kt < nk; kt++) {
        As[acol + 0][arow] = pa.x;
        As[acol + 1][arow] = pa.y;
        As[acol + 2][arow] = pa.z;
        As[acol + 3][arow] = pa.w;
        *(float4*)&Bs[brow][bcol] = pb;
        __syncthreads();

        if (kt + 1 < nk) {   // register prefetch of next tile
            pa = *(const float4*)(Ag + (kt + 1) * 8);
            pb = *(const float4*)(Wg + (size_t)(kt + 1) * 8 * N);
        }

        #pragma unroll
        for (int k = 0; k < 8; k++) {
            float a[8];
            *(float4*)&a[0] = *(const float4*)&As[k][ty * 4];
            *(float4*)&a[4] = *(const float4*)&As[k][64 + ty * 4];
            u64 b2[4];
            b2[0] = *(const u64*)&Bs[k][tx * 4];
            b2[1] = *(const u64*)&Bs[k][tx * 4 + 2];
            b2[2] = *(const u64*)&Bs[k][64 + tx * 4];
            b2[3] = *(const u64*)&Bs[k][64 + tx * 4 + 2];
            #pragma unroll
            for (int i = 0; i < 8; i++) {
                u64 ad = pk2(a[i], a[i]);
                #pragma unroll
                for (int jp = 0; jp < 4; jp++) fma2(c2[i][jp], ad, b2[jp]);
            }
        }
        __syncthreads();
    }

    // epilogue
    #pragma unroll
    for (int ri = 0; ri < 2; ri++)
    #pragma unroll
    for (int ii = 0; ii < 4; ii++) {
        const int i = ri * 4 + ii;
        const int r = crow + ri * 64 + ty * 4 + ii;
        #pragma unroll
        for (int ci = 0; ci < 2; ci++) {
            const int n0 = ccol + ci * 64 + tx * 4;
            float2 p0 = upk(c2[i][ci * 2 + 0]);
            float2 p1 = upk(c2[i][ci * 2 + 1]);
            float v[4] = { p0.x, p0.y, p1.x, p1.y };
            #pragma unroll
            for (int j = 0; j < 4; j++) v[j] += bias[n0 + j];
            if (MODE == 0) {
                if (n0 < C_) {
                    #pragma unroll
                    for (int j = 0; j < 4; j++) v[j] = (v[j] + bQ[n0 + j]) * 0.125f; // fold 1/sqrt(64)
                } else if (n0 < 2 * C_) {
                    #pragma unroll
                    for (int j = 0; j < 4; j++) v[j] = v[j] + bK[n0 - C_ + j];
                }
            }
            *(float4*)&Cout[(size_t)r * N + n0] = make_float4(v[0], v[1], v[2], v[3]);
        }
    }
}

// ---------------------------------------------------------------------------
// Flash attention (fp32, packed f32x2 FMA). One CTA = (b, h, 64-row q tile).
// Bq=Bk=64, D=64. 256 threads as 16(ty) x 16(tx), 4x4 microtiles.
// Smem: Qs natural [i][d]; KP holds K transposed+swizzled [d][j] then reused
// for P [i][j]; Vs natural [k][d].  48 KB static.
// ---------------------------------------------------------------------------
__global__ __launch_bounds__(256) void attn_kernel()
{
    __shared__ float Qs[64 * 64];
    __shared__ float KP[64 * 64];
    __shared__ float Vs[64 * 64];

    const int tid = threadIdx.x;
    const int tx = tid & 15, ty = tid >> 4;
    const int qt = blockIdx.x, h = blockIdx.y, b = blockIdx.z;
    const int q0 = qt * 64;
    const size_t rowbase = (size_t)b * T_ * C3_ + (size_t)h * D_;

    // Load Q tile (bQ added + 1/sqrt(D) folded during GEMM epilogue)
    #pragma unroll
    for (int r = 0; r < 4; r++) {
        int cidx = tid + 256 * r;
        int i = cidx >> 4, f = cidx & 15;
        *(float4*)&Qs[i * 64 + f * 4] =
            *(const float4*)&g_qkv[rowbase + (size_t)(q0 + i) * C3_ + f * 4];
    }

    const float NEG = -1e30f;
    float m[4], l[4];
    u64 o2[4][2];
    #pragma unroll
    for (int ii = 0; ii < 4; ii++) {
        m[ii] = NEG; l[ii] = 0.f;
        o2[ii][0] = 0ull; o2[ii][1] = 0ull;
    }

    for (int kt = 0; kt <= qt; kt++) {
        const int k0 = kt * 64;
        __syncthreads();  // previous iteration's KP/Vs readers done (covers Qs store->read too)

        // Load K (transposed + XOR swizzle) and V (natural)
        #pragma unroll
        for (int r = 0; r < 4; r++) {
            int cidx = tid + 256 * r;
            int j = cidx >> 4, f = cidx & 15;
            size_t gro = rowbase + (size_t)(k0 + j) * C3_;
            float4 kv = *(const float4*)&g_qkv[gro + C_ + f * 4];
            int pcol = (((j >> 2) ^ f) << 2) + (j & 3);
            KP[(4 * f + 0) * 64 + pcol] = kv.x;
            KP[(4 * f + 1) * 64 + pcol] = kv.y;
            KP[(4 * f + 2) * 64 + pcol] = kv.z;
            KP[(4 * f + 3) * 64 + pcol] = kv.w;
            *(float4*)&Vs[j * 64 + f * 4] =
                *(const float4*)&g_qkv[gro + 2 * C_ + f * 4];
        }
        __syncthreads();

        // S = Q K^T   (packed pairs along k-columns)
        u64 s2[4][2];
        #pragma unroll
        for (int ii = 0; ii < 4; ii++) { s2[ii][0] = 0ull; s2[ii][1] = 0ull; }

        #pragma unroll 8
        for (int d = 0; d < 64; d++) {
            float a0 = Qs[(ty * 4 + 0) * 64 + d];
            float a1 = Qs[(ty * 4 + 1) * 64 + d];
            float a2 = Qs[(ty * 4 + 2) * 64 + d];
            float a3 = Qs[(ty * 4 + 3) * 64 + d];
            const int sw = d * 64 + ((tx ^ (d >> 2)) << 2);
            u64 b0 = *(const u64*)&KP[sw];
            u64 b1 = *(const u64*)&KP[sw + 2];
            u64 ad;
            ad = pk2(a0, a0); fma2(s2[0][0], ad, b0); fma2(s2[0][1], ad, b1);
            ad = pk2(a1, a1); fma2(s2[1][0], ad, b0); fma2(s2[1][1], ad, b1);
            ad = pk2(a2, a2); fma2(s2[2][0], ad, b0); fma2(s2[2][1], ad, b1);
            ad = pk2(a3, a3); fma2(s2[3][0], ad, b0); fma2(s2[3][1], ad, b1);
        }

        float s[4][4];
        #pragma unroll
        for (int ii = 0; ii < 4; ii++) {
            float2 p0 = upk(s2[ii][0]), p1 = upk(s2[ii][1]);
            s[ii][0] = p0.x; s[ii][1] = p0.y; s[ii][2] = p1.x; s[ii][3] = p1.y;
        }

        if (kt == qt) {  // diagonal tile: causal mask
            #pragma unroll
            for (int ii = 0; ii < 4; ii++)
                #pragma unroll
                for (int j = 0; j < 4; j++)
                    if (tx * 4 + j > ty * 4 + ii) s[ii][j] = NEG;
        }

        // online softmax (row reductions across 16 tx lanes)
        #pragma unroll
        for (int ii = 0; ii < 4; ii++) {
            float mt = fmaxf(fmaxf(s[ii][0], s[ii][1]), fmaxf(s[ii][2], s[ii][3]));
            mt = fmaxf(mt, __shfl_xor_sync(0xffffffffu, mt, 1));
            mt = fmaxf(mt, __shfl_xor_sync(0xffffffffu, mt, 2));
            mt = fmaxf(mt, __shfl_xor_sync(0xffffffffu, mt, 4));
            mt = fmaxf(mt, __shfl_xor_sync(0xffffffffu, mt, 8));
            float mnew = fmaxf(m[ii], mt);
            float alpha = __expf(m[ii] - mnew);
            float sum = 0.f;
            #pragma unroll
            for (int j = 0; j < 4; j++) {
                s[ii][j] = __expf(s[ii][j] - mnew);
                sum += s[ii][j];
            }
            sum += __shfl_xor_sync(0xffffffffu, sum, 1);
            sum += __shfl_xor_sync(0xffffffffu, sum, 2);
            sum += __shfl_xor_sync(0xffffffffu, sum, 4);
            sum += __shfl_xor_sync(0xffffffffu, sum, 8);
            l[ii] = l[ii] * alpha + sum;
            m[ii] = mnew;
            u64 ad = pk2(alpha, alpha);
            mul2(o2[ii][0], ad);
            mul2(o2[ii][1], ad);
        }

        __syncthreads();   // all reads of KP done -> safe to overwrite with P
        #pragma unroll
        for (int ii = 0; ii < 4; ii++)
            *(float4*)&KP[(ty * 4 + ii) * 64 + tx * 4] =
                make_float4(s[ii][0], s[ii][1], s[ii][2], s[ii][3]);
        __syncthreads();

        // O += P @ V  (packed pairs along d-columns)
        #pragma unroll 8
        for (int k = 0; k < 64; k++) {
            float a0 = KP[(ty * 4 + 0) * 64 + k];
            float a1 = KP[(ty * 4 + 1) * 64 + k];
            float a2 = KP[(ty * 4 + 2) * 64 + k];
            float a3 = KP[(ty * 4 + 3) * 64 + k];
            u64 b0 = *(const u64*)&Vs[k * 64 + tx * 4];
            u64 b1 = *(const u64*)&Vs[k * 64 + tx * 4 + 2];
            u64 ad;
            ad = pk2(a0, a0); fma2(o2[0][0], ad, b0); fma2(o2[0][1], ad, b1);
            ad = pk2(a1, a1); fma2(o2[1][0], ad, b0); fma2(o2[1][1], ad, b1);
            ad = pk2(a2, a2); fma2(o2[2][0], ad, b0); fma2(o2[2][1], ad, b1);
            ad = pk2(a3, a3); fma2(o2[3][0], ad, b0); fma2(o2[3][1], ad, b1);
        }
    }

    // normalize and write y in [b, t, h, d] layout (columns h*D + d)
    #pragma unroll
    for (int ii = 0; ii < 4; ii++) {
        float inv = 1.f / l[ii];
        float2 p0 = upk(o2[ii][0]), p1 = upk(o2[ii][1]);
        *(float4*)&g_y[(size_t)(b * T_ + q0 + ty * 4 + ii) * C_ + h * D_ + tx * 4] =
            make_float4(p0.x * inv, p0.y * inv, p1.x * inv, p1.y * inv);
    }
}

// ---------------------------------------------------------------------------
extern "C" void kernel_launch(void* const* d_in, const int* in_sizes, int n_in,
                              void* d_out, int out_size)
{
    const float* x      = (const float*)d_in[0];
    const float* W_attn = (const float*)d_in[1];
    const float* b_attn = (const float*)d_in[2];
    const float* bQ     = (const float*)d_in[3];
    const float* bK     = (const float*)d_in[4];
    const float* W_proj = (const float*)d_in[5];
    const float* b_proj = (const float*)d_in[6];
    float* out = (float*)d_out;

    float *qkv_p = nullptr, *y_p = nullptr;
    cudaGetSymbolAddress((void**)&qkv_p, g_qkv);
    cudaGetSymbolAddress((void**)&y_p, g_y);

    // 1) qkv = x @ W_attn + b_attn (+bQ,*0.125 | +bK)        [8192, 3072]
    sgemm_kernel<0><<<dim3(C3_ / 128, BT_ / 128), 256>>>(
        x, W_attn, b_attn, bQ, bK, qkv_p, BT_, C3_, C_);

    // 2) flash attention -> g_y                              [8192, 1024]
    attn_kernel<<<dim3(T_ / 64, NH_, B_), 256>>>();

    // 3) out = y @ W_proj + b_proj                           [8192, 1024]
    sgemm_kernel<1><<<dim3(C_ / 128, BT_ / 128), 256>>>(
        y_p, W_proj, b_proj, nullptr, nullptr, out, BT_, C_, C_);
}